// round 3
// baseline (speedup 1.0000x reference)
#include <cuda_runtime.h>
#include <math.h>

#define SEQ_L 64
#define NSTOCK 8000
#define NNEWS 1600
#define C_IN 128
#define HID 256
#define NEDGE 32000
#define G3 768            // 3*HID
#define CM 384            // C_IN + HID
#define NT 256            // threads per block
#define NBLK 296          // 2 blocks per SM on 148+ SMs (GB300 has 152)

// ---------------- scratch (static device memory; no allocs allowed) ----------
__device__ float g_acc_news[NNEWS * C_IN];
__device__ float g_cnt_news[NNEWS];
__device__ float g_center[NNEWS * C_IN];
__device__ float g_mc[NNEWS * HID];
__device__ float g_acc_stock[NSTOCK * CM];
__device__ float g_cnt_stock[NSTOCK];
__device__ float g_gi_n[NNEWS * G3];
__device__ float g_gh_n[NNEWS * G3];
__device__ float g_gi_s[NSTOCK * G3];
__device__ float g_gh_s[NSTOCK * G3];
__device__ unsigned g_bar_count = 0;

// ---------------- software grid barrier (monotonic, no reset race) -----------
// All writes before the barrier are made visible via __threadfence (gpu scope),
// which also emits CCTL.IVALL on sm_103a -> L1 invalidated -> plain loads after
// the barrier observe other blocks' writes.
__device__ __forceinline__ void grid_sync() {
    __syncthreads();
    __threadfence();
    if (threadIdx.x == 0) {
        unsigned G = gridDim.x;
        unsigned arrival = atomicAdd(&g_bar_count, 1u) + 1u;
        unsigned target = ((arrival + G - 1u) / G) * G;
        volatile unsigned* vc = &g_bar_count;
        while (*vc < target) { __nanosleep(64); }
    }
    __syncthreads();
    __threadfence();
}

// ---------------- 64x64 fp32 GEMM tile: C[m0:+64, n0:+64] += A @ W^T + bias --
// A[M,K], W[768,K] row-major; C row stride = 768. 256 threads, 4x4 microtile.
__device__ __forceinline__ void gemm_tile(
    const float* __restrict__ A, const float* __restrict__ W,
    const float* __restrict__ bias, float* __restrict__ Cc,
    int K, int m0, int n0, float (*As)[65], float (*Bs)[65]) {
    int tid = threadIdx.x;
    int tx = tid & 15;          // 16 col groups of 4
    int ty = tid >> 4;          // 16 row groups of 4
    int lk = tid & 15;
    int lm = tid >> 4;
    float acc[4][4] = {};
    for (int kt = 0; kt < K; kt += 16) {
#pragma unroll
        for (int i = 0; i < 4; i++) {
            As[lk][lm + i * 16] = A[(size_t)(m0 + lm + i * 16) * K + kt + lk];
            Bs[lk][lm + i * 16] = W[(size_t)(n0 + lm + i * 16) * K + kt + lk];
        }
        __syncthreads();
#pragma unroll
        for (int k = 0; k < 16; k++) {
            float a[4], b[4];
#pragma unroll
            for (int i = 0; i < 4; i++) a[i] = As[k][ty * 4 + i];
#pragma unroll
            for (int j = 0; j < 4; j++) b[j] = Bs[k][tx * 4 + j];
#pragma unroll
            for (int i = 0; i < 4; i++)
#pragma unroll
                for (int j = 0; j < 4; j++) acc[i][j] += a[i] * b[j];
        }
        __syncthreads();
    }
#pragma unroll
    for (int i = 0; i < 4; i++) {
        int m = m0 + ty * 4 + i;
#pragma unroll
        for (int j = 0; j < 4; j++) {
            int n = n0 + tx * 4 + j;
            Cc[(size_t)m * G3 + n] = acc[i][j] + bias[n];
        }
    }
}

// ---------------- GRU gate fusion --------------------------------------------
__device__ __forceinline__ void gate_apply(const float* __restrict__ gi,
                                           const float* __restrict__ gh,
                                           float* __restrict__ h, int M,
                                           int gtid, int nthr) {
    int total = M * HID;
    for (int idx = gtid; idx < total; idx += nthr) {
        int m = idx >> 8;          // HID == 256
        int j = idx & 255;
        const float* gim = gi + (size_t)m * G3;
        const float* ghm = gh + (size_t)m * G3;
        float r = 1.0f / (1.0f + __expf(-(gim[j] + ghm[j])));
        float z = 1.0f / (1.0f + __expf(-(gim[HID + j] + ghm[HID + j])));
        float n = tanhf(gim[2 * HID + j] + r * ghm[2 * HID + j]);
        h[idx] = (1.0f - z) * n + z * h[idx];
    }
}

// ---------------- the persistent mega-kernel ---------------------------------
__global__ __launch_bounds__(NT, 2)
void mega_kernel(const float* __restrict__ inputs, const int* __restrict__ ei,
                 const float* __restrict__ h_start, const float* __restrict__ hi_start,
                 const float* __restrict__ mc_start,
                 const float* __restrict__ Wih_c,  const float* __restrict__ Whh_c,
                 const float* __restrict__ bih_c,  const float* __restrict__ bhh_c,
                 const float* __restrict__ Wih_lh, const float* __restrict__ Whh_lh,
                 const float* __restrict__ bih_lh, const float* __restrict__ bhh_lh,
                 const float* __restrict__ Wih_li, const float* __restrict__ Whh_li,
                 const float* __restrict__ bih_li, const float* __restrict__ bhh_li,
                 float* __restrict__ m_out, float* __restrict__ h_out,
                 float* __restrict__ hi_out) {
    __shared__ float As[16][65];
    __shared__ float Bs[16][65];

    const int gtid = blockIdx.x * NT + threadIdx.x;
    const int nthr = gridDim.x * NT;
    const int gwarp = gtid >> 5;
    const int lane = threadIdx.x & 31;
    const int nwarp = nthr >> 5;

    // ---- init recurrent state ----
    for (int i = gtid; i < NSTOCK * HID; i += nthr) {
        h_out[i] = h_start[i & 255];
        hi_out[i] = hi_start[i & 255];
    }
    for (int i = gtid; i < NNEWS * HID; i += nthr) g_mc[i] = mc_start[i & 255];
    grid_sync();

    for (int t = 0; t < SEQ_L; t++) {
        const float* xt = inputs + (size_t)t * NSTOCK * C_IN;
        const int* news = ei + (size_t)t * 2 * NEDGE;
        const int* stck = news + NEDGE;

        // ---- P0: zero accumulators ----
        for (int i = gtid; i < NNEWS * C_IN; i += nthr) g_acc_news[i] = 0.0f;
        for (int i = gtid; i < NNEWS; i += nthr) g_cnt_news[i] = 0.0f;
        for (int i = gtid; i < NSTOCK * CM; i += nthr) g_acc_stock[i] = 0.0f;
        for (int i = gtid; i < NSTOCK; i += nthr) g_cnt_stock[i] = 0.0f;
        grid_sync();

        // ---- P1: scatter stocks -> news (sum x[stck] at news) ----
        for (int e = gwarp; e < NEDGE; e += nwarp) {
            int n = news[e];
            int s = stck[e];
            float4 v = ((const float4*)(xt + (size_t)s * C_IN))[lane];
            float* dst = g_acc_news + (size_t)n * C_IN + lane * 4;
            atomicAdd(dst + 0, v.x);
            atomicAdd(dst + 1, v.y);
            atomicAdd(dst + 2, v.z);
            atomicAdd(dst + 3, v.w);
            if (lane == 0) atomicAdd(&g_cnt_news[n], 1.0f);
        }
        grid_sync();

        // ---- P2: normalize -> center_m ----
        for (int i = gtid; i < NNEWS * C_IN; i += nthr) {
            float c = g_cnt_news[i >> 7];           // C_IN == 128
            g_center[i] = g_acc_news[i] / fmaxf(c, 1.0f);
        }
        grid_sync();

        // ---- P3: GEMMs gi_c, gh_c (news) + gi_li, gh_li (stocks) ----
        // tile counts: 25*12=300 (news), 125*12=1500 (stocks)
        for (int tile = blockIdx.x; tile < 3600; tile += gridDim.x) {
            const float *A, *W, *B; float* Cc; int K, idx;
            if (tile < 1500)      { A = xt;       W = Wih_li; B = bih_li; Cc = g_gi_s; K = C_IN; idx = tile; }
            else if (tile < 3000) { A = hi_out;   W = Whh_li; B = bhh_li; Cc = g_gh_s; K = HID;  idx = tile - 1500; }
            else if (tile < 3300) { A = g_center; W = Wih_c;  B = bih_c;  Cc = g_gi_n; K = C_IN; idx = tile - 3000; }
            else                  { A = g_mc;     W = Whh_c;  B = bhh_c;  Cc = g_gh_n; K = HID;  idx = tile - 3300; }
            int mt = idx / 12, nt = idx % 12;
            gemm_tile(A, W, B, Cc, K, mt * 64, nt * 64, As, Bs);
        }
        grid_sync();

        // ---- P4: gates: m_c update (news) + h_input update (stocks) ----
        gate_apply(g_gi_n, g_gh_n, g_mc, NNEWS, gtid, nthr);
        gate_apply(g_gi_s, g_gh_s, hi_out, NSTOCK, gtid, nthr);
        grid_sync();

        // ---- P5: scatter news -> stocks (sum [center_m, m_c][news] at stck) ----
        for (int e = gwarp; e < NEDGE; e += nwarp) {
            int n = news[e];
            int s = stck[e];
#pragma unroll
            for (int j = 0; j < 3; j++) {
                int c = (lane + j * 32) * 4;        // 0..380
                float4 v;
                if (c < C_IN) v = *(const float4*)(g_center + (size_t)n * C_IN + c);
                else          v = *(const float4*)(g_mc + (size_t)n * HID + (c - C_IN));
                float* dst = g_acc_stock + (size_t)s * CM + c;
                atomicAdd(dst + 0, v.x);
                atomicAdd(dst + 1, v.y);
                atomicAdd(dst + 2, v.z);
                atomicAdd(dst + 3, v.w);
            }
            if (lane == 0) atomicAdd(&g_cnt_stock[s], 1.0f);
        }
        grid_sync();

        // ---- P6: normalize -> m_out ----
        for (int i = gtid; i < NSTOCK * CM; i += nthr) {
            float c = g_cnt_stock[i / CM];
            m_out[i] = g_acc_stock[i] / fmaxf(c, 1.0f);
        }
        grid_sync();

        // ---- P7: GEMMs gi_lh (K=384), gh_lh (K=256) ----
        for (int tile = blockIdx.x; tile < 3000; tile += gridDim.x) {
            const float *A, *W, *B; float* Cc; int K, idx;
            if (tile < 1500) { A = m_out; W = Wih_lh; B = bih_lh; Cc = g_gi_s; K = CM;  idx = tile; }
            else             { A = h_out; W = Whh_lh; B = bhh_lh; Cc = g_gh_s; K = HID; idx = tile - 1500; }
            int mt = idx / 12, nt = idx % 12;
            gemm_tile(A, W, B, Cc, K, mt * 64, nt * 64, As, Bs);
        }
        grid_sync();

        // ---- P8: gate: h update ----
        gate_apply(g_gi_s, g_gh_s, h_out, NSTOCK, gtid, nthr);
        grid_sync();
    }
}

// ---------------- launch -----------------------------------------------------
extern "C" void kernel_launch(void* const* d_in, const int* in_sizes, int n_in,
                              void* d_out, int out_size) {
    const float* inputs   = (const float*)d_in[0];   // [64, 8000, 128]
    const int*   ei       = (const int*)d_in[1];     // [64, 2, 32000]
    const float* h_start  = (const float*)d_in[2];
    const float* hi_start = (const float*)d_in[3];
    const float* mc_start = (const float*)d_in[4];
    const float* Wih_c  = (const float*)d_in[5];
    const float* Whh_c  = (const float*)d_in[6];
    const float* bih_c  = (const float*)d_in[7];
    const float* bhh_c  = (const float*)d_in[8];
    const float* Wih_lh = (const float*)d_in[9];
    const float* Whh_lh = (const float*)d_in[10];
    const float* bih_lh = (const float*)d_in[11];
    const float* bhh_lh = (const float*)d_in[12];
    const float* Wih_li = (const float*)d_in[13];
    const float* Whh_li = (const float*)d_in[14];
    const float* bih_li = (const float*)d_in[15];
    const float* bhh_li = (const float*)d_in[16];

    float* out    = (float*)d_out;
    float* m_out  = out;                                // [8000, 384]
    float* h_out  = out + (size_t)NSTOCK * CM;          // [8000, 256]
    float* hi_out = h_out + (size_t)NSTOCK * HID;       // [8000, 256]

    unsigned* bar = nullptr;
    cudaGetSymbolAddress((void**)&bar, g_bar_count);
    cudaMemsetAsync(bar, 0, sizeof(unsigned));

    mega_kernel<<<NBLK, NT>>>(inputs, ei, h_start, hi_start, mc_start,
                              Wih_c, Whh_c, bih_c, bhh_c,
                              Wih_lh, Whh_lh, bih_lh, bhh_lh,
                              Wih_li, Whh_li, bih_li, bhh_li,
                              m_out, h_out, hi_out);
}